// round 16
// baseline (speedup 1.0000x reference)
#include <cuda_runtime.h>
#include <cuda_bf16.h>
#include <cstdint>

// Problem constants (fixed by dataset)
#define BATCH   131072
#define UNITS   512
#define DIMK    64
#define M_TILE  128
#define N_TILES (BATCH / M_TILE)   // 1024
#define GRID_X  148
#define NTHREADS 256               // 8 warps; each warp owns a 64-col strip
#define TILES_LO 6                 // 1024 = 12*6 + 136*7
#define CTAS_LO  12                // first 12 CTAs take 6 tiles, rest take 7

// ---------------- SMEM layout ----------------
static constexpr int ROW_BYTES = 144;                     // bf16 rows padded (ldmatrix)
static constexpr int SM_WSQ  = 0;                         // 512 f32 -> 2048
static constexpr int SM_XSQ0 = 2048;                      // 128 f32 -> 2560
static constexpr int SM_XSQ1 = 2560;                      // 128 f32 -> 3072
static constexpr int SM_X0   = 3072;                      // 128*144 -> 21504
static constexpr int SM_X1   = 21504;                     // -> 39936
static constexpr int SM_WST  = 39936;                     // 512*144 -> 113664
static constexpr int SM_STG  = 113664;                    // 8 warps * 2 * 4KB -> 179200
static constexpr int SMEM_TOTAL = SM_STG + 8 * 8192;

static __device__ __forceinline__ uint32_t smem_u32(const void* p) {
    uint32_t a;
    asm("{ .reg .u64 t; cvta.to.shared.u64 t, %1; cvt.u32.u64 %0, t; }" : "=r"(a) : "l"(p));
    return a;
}

static __device__ __forceinline__ void ldsm_x4(uint32_t& r0, uint32_t& r1, uint32_t& r2,
                                               uint32_t& r3, uint32_t addr) {
    asm volatile("ldmatrix.sync.aligned.m8n8.x4.shared.b16 {%0,%1,%2,%3}, [%4];"
                 : "=r"(r0), "=r"(r1), "=r"(r2), "=r"(r3) : "r"(addr));
}

static __device__ __forceinline__ void mma_bf16(float c[4], uint32_t a0, uint32_t a1,
                                                uint32_t a2, uint32_t a3,
                                                uint32_t b0, uint32_t b1) {
    asm volatile(
        "mma.sync.aligned.m16n8k16.row.col.f32.bf16.bf16.f32 "
        "{%0,%1,%2,%3}, {%4,%5,%6,%7}, {%8,%9}, {%0,%1,%2,%3};"
        : "+f"(c[0]), "+f"(c[1]), "+f"(c[2]), "+f"(c[3])
        : "r"(a0), "r"(a1), "r"(a2), "r"(a3), "r"(b0), "r"(b1));
}

static __device__ __forceinline__ uint32_t pack_bf16(float a, float b) {
    __nv_bfloat162 t = __floats2bfloat162_rn(a, b);
    return *reinterpret_cast<uint32_t*>(&t);
}

__global__ void __launch_bounds__(NTHREADS, 1)
l2dist_kernel(const float* __restrict__ x, const float* __restrict__ w,
              float* __restrict__ out) {
    extern __shared__ char smem[];
    const uint32_t sb = smem_u32(smem);
    const int tid  = threadIdx.x;
    const int wid  = tid >> 5;
    const int lane = tid & 31;

    const int ld_r0 = tid >> 4;
    const int ld_k  = (tid & 15) * 4;

    // ---- Contiguous tile range for this CTA ----
    const int bid = blockIdx.x;
    const int t_begin = (bid < CTAS_LO) ? bid * TILES_LO
                                        : CTAS_LO * TILES_LO + (bid - CTAS_LO) * (TILES_LO + 1);
    const int t_end   = t_begin + ((bid < CTAS_LO) ? TILES_LO : TILES_LO + 1);

    int t = t_begin;

    // ---- Issue first tile's x LDG EARLY: latency hides under W staging ----
    float4 fv[8];
    {
        #pragma unroll
        for (int it = 0; it < 8; it++)
            fv[it] = __ldcs(reinterpret_cast<const float4*>(
                x + (size_t)(t * M_TILE + it * 16 + ld_r0) * DIMK + ld_k));
    }

    // ---- WARP-LOCAL W staging: warp wid loads its own 64 rows + wsq ----
    const int n_w = wid * 64;
    {
        #pragma unroll
        for (int rr = 0; rr < 2; rr++) {
            const int u = n_w + rr * 32 + lane;           // within this warp's strip
            const float* wr = w + (size_t)u * DIMK;
            float sq = 0.f;
            #pragma unroll
            for (int g = 0; g < 8; g++) {
                float4 a = *reinterpret_cast<const float4*>(wr + 8 * g);
                float4 b = *reinterpret_cast<const float4*>(wr + 8 * g + 4);
                sq += a.x * a.x + a.y * a.y + a.z * a.z + a.w * a.w
                    + b.x * b.x + b.y * b.y + b.z * b.z + b.w * b.w;
                uint4 pk;
                pk.x = pack_bf16(a.x, a.y); pk.y = pack_bf16(a.z, a.w);
                pk.z = pack_bf16(b.x, b.y); pk.w = pack_bf16(b.z, b.w);
                *reinterpret_cast<uint4*>(smem + SM_WST + u * ROW_BYTES + g * 16) = pk;
            }
            *reinterpret_cast<float*>(smem + SM_WSQ + u * 4) = sq;
        }
    }
    __syncwarp();   // warp-local: Bf depends only on this warp's strip

    // ---- Load this warp's B fragments ONCE (64 cols x 64 k) : 64 regs ----
    uint32_t Bf[4][4][4];   // [n16-group][ks][frag]
    {
        const uint32_t bb = sb + SM_WST + (uint32_t)(lane & 15) * ROW_BYTES
                          + (uint32_t)((lane >> 4) * 16);
        #pragma unroll
        for (int g = 0; g < 4; g++)
            #pragma unroll
            for (int ks = 0; ks < 4; ks++)
                ldsm_x4(Bf[g][ks][0], Bf[g][ks][1], Bf[g][ks][2], Bf[g][ks][3],
                        bb + (uint32_t)(n_w + g * 16) * ROW_BYTES + ks * 32);
    }

    const int gq = lane >> 2;           // 0..7  (C-frag row within 8-group)
    const int qq = lane & 3;            // 0..3  (C-frag col pair)

    // readback/store mapping: lane covers 4 consecutive cols of 2 rows per iter
    const int rd_row  = lane >> 4;      // 0/1
    const int rd_colg = lane & 15;      // 0..15 -> cols rd_colg*4..+3
    const float4 ws4 = *reinterpret_cast<const float4*>(
        smem + SM_WSQ + (n_w + rd_colg * 4) * 4);   // within own strip (warp-local)

    const uint32_t a_lane_off = (uint32_t)(lane & 15) * ROW_BYTES
                              + (uint32_t)((lane >> 4) * 16);
    char* const stg0 = smem + SM_STG + wid * 8192;   // two 4KB fp32 buffers

    // ---- Commit first tile (data already in registers) ----
    {
        #pragma unroll
        for (int it = 0; it < 8; it++) {
            const int r = it * 16 + ld_r0;
            float4 v = fv[it];
            float sq = v.x * v.x + v.y * v.y + v.z * v.z + v.w * v.w;
            sq += __shfl_xor_sync(0xffffffffu, sq, 1);
            sq += __shfl_xor_sync(0xffffffffu, sq, 2);
            sq += __shfl_xor_sync(0xffffffffu, sq, 4);
            sq += __shfl_xor_sync(0xffffffffu, sq, 8);
            uint2 pk; pk.x = pack_bf16(v.x, v.y); pk.y = pack_bf16(v.z, v.w);
            *reinterpret_cast<uint2*>(smem + SM_X0 + r * ROW_BYTES + ld_k * 2) = pk;
            if ((tid & 15) == 0)
                *reinterpret_cast<float*>(smem + SM_XSQ0 + r * 4) = sq;
        }
    }
    __syncthreads();

    int cur = 0;
    for (; t < t_end; t++, cur ^= 1) {
        const int tn = t + 1;
        const bool more = (tn < t_end);
        const uint32_t xb = cur ? SM_X1 : SM_X0;
        const uint32_t xq = cur ? SM_XSQ1 : SM_XSQ0;
        const uint32_t xbn = cur ? SM_X0 : SM_X1;
        const uint32_t xqn = cur ? SM_XSQ0 : SM_XSQ1;
        const int row0 = t * M_TILE;

        float4 pvA[4], pvB[4];
        if (more) {
            #pragma unroll
            for (int it = 0; it < 4; it++)
                pvA[it] = __ldcs(reinterpret_cast<const float4*>(
                    x + (size_t)(tn * M_TILE + it * 16 + ld_r0) * DIMK + ld_k));
        }

        #pragma unroll
        for (int rb = 0; rb < 8; rb++) {
            if (rb == 4 && more) {
                #pragma unroll
                for (int it = 0; it < 4; it++)
                    pvB[it] = __ldcs(reinterpret_cast<const float4*>(
                        x + (size_t)(tn * M_TILE + (it + 4) * 16 + ld_r0) * DIMK + ld_k));
            }
            // spread the next-tile commit: first half at rb==6 (pvA freed early)
            if (rb == 6 && more) {
                #pragma unroll
                for (int it = 0; it < 4; it++) {
                    const int r = it * 16 + ld_r0;
                    float4 v = pvA[it];
                    float sq = v.x * v.x + v.y * v.y + v.z * v.z + v.w * v.w;
                    sq += __shfl_xor_sync(0xffffffffu, sq, 1);
                    sq += __shfl_xor_sync(0xffffffffu, sq, 2);
                    sq += __shfl_xor_sync(0xffffffffu, sq, 4);
                    sq += __shfl_xor_sync(0xffffffffu, sq, 8);
                    uint2 pk; pk.x = pack_bf16(v.x, v.y); pk.y = pack_bf16(v.z, v.w);
                    *reinterpret_cast<uint2*>(smem + xbn + r * ROW_BYTES + ld_k * 2) = pk;
                    if ((tid & 15) == 0)
                        *reinterpret_cast<float*>(smem + xqn + r * 4) = sq;
                }
            }

            char* const stg = stg0 + (rb & 1) * 4096;   // double-buffered staging
            const uint32_t abase = sb + xb + (uint32_t)(rb * 16) * ROW_BYTES + a_lane_off;
            float acc[8][4];
            #pragma unroll
            for (int i = 0; i < 8; i++)
                #pragma unroll
                for (int j = 0; j < 4; j++) acc[i][j] = 0.f;

            #pragma unroll
            for (int ks = 0; ks < 4; ks++) {
                uint32_t a0, a1, a2, a3;
                ldsm_x4(a0, a1, a2, a3, abase + ks * 32);
                #pragma unroll
                for (int g = 0; g < 4; g++) {
                    mma_bf16(acc[2 * g + 0], a0, a1, a2, a3, Bf[g][ks][0], Bf[g][ks][2]);
                    mma_bf16(acc[2 * g + 1], a0, a1, a2, a3, Bf[g][ks][1], Bf[g][ks][3]);
                }
            }

            // ---- Stage raw fp32 acc (STS.64), 8B granules h ^= (gq<<2) ----
            #pragma unroll
            for (int nb = 0; nb < 8; nb++) {
                const uint32_t h  = (uint32_t)(gq * 32 + nb * 4 + qq) ^ ((uint32_t)gq << 2);
                const uint32_t hh = h + 8 * 32;   // row gq+8: same swizzle
                *reinterpret_cast<float2*>(stg + h * 8)
                    = make_float2(acc[nb][0], acc[nb][1]);
                *reinterpret_cast<float2*>(stg + hh * 8)
                    = make_float2(acc[nb][2], acc[nb][3]);
            }
            __syncwarp();
            // no trailing syncwarp: next rb uses the other staging buffer

            // ---- Read back row-major (LDS.128), epilogue, full-line STG.128 ----
            #pragma unroll
            for (int i = 0; i < 8; i++) {
                const int row = i * 2 + rd_row;
                const uint32_t g16 = (uint32_t)(row * 16 + rd_colg)
                                   ^ (((uint32_t)(row & 7)) << 1);
                const float4 v = *reinterpret_cast<const float4*>(stg + g16 * 16);
                const float xsv = *reinterpret_cast<const float*>(
                    smem + xq + (rb * 16 + row) * 4);
                float4 o;
                o.x = fmaf(-2.f, v.x, xsv + ws4.x);
                o.y = fmaf(-2.f, v.y, xsv + ws4.y);
                o.z = fmaf(-2.f, v.z, xsv + ws4.z);
                o.w = fmaf(-2.f, v.w, xsv + ws4.w);
                __stcs(reinterpret_cast<float4*>(
                    out + (size_t)(row0 + rb * 16 + row) * UNITS + n_w + rd_colg * 4), o);
            }
        }

        // ---- Commit second half of prefetched tile ----
        if (more) {
            #pragma unroll
            for (int it = 4; it < 8; it++) {
                const int r = it * 16 + ld_r0;
                float4 v = pvB[it - 4];
                float sq = v.x * v.x + v.y * v.y + v.z * v.z + v.w * v.w;
                sq += __shfl_xor_sync(0xffffffffu, sq, 1);
                sq += __shfl_xor_sync(0xffffffffu, sq, 2);
                sq += __shfl_xor_sync(0xffffffffu, sq, 4);
                sq += __shfl_xor_sync(0xffffffffu, sq, 8);
                uint2 pk; pk.x = pack_bf16(v.x, v.y); pk.y = pack_bf16(v.z, v.w);
                *reinterpret_cast<uint2*>(smem + xbn + r * ROW_BYTES + ld_k * 2) = pk;
                if ((tid & 15) == 0)
                    *reinterpret_cast<float*>(smem + xqn + r * 4) = sq;
            }
        }
        __syncthreads();
    }
}

extern "C" void kernel_launch(void* const* d_in, const int* in_sizes, int n_in,
                              void* d_out, int out_size) {
    const float* x = (const float*)d_in[0];
    const float* w = (const float*)d_in[1];
    float* out = (float*)d_out;
    cudaFuncSetAttribute(l2dist_kernel, cudaFuncAttributeMaxDynamicSharedMemorySize, SMEM_TOTAL);
    l2dist_kernel<<<GRID_X, NTHREADS, SMEM_TOTAL>>>(x, w, out);
}

// round 17
// speedup vs baseline: 1.0128x; 1.0128x over previous
#include <cuda_runtime.h>
#include <cuda_bf16.h>
#include <cstdint>

// Problem constants (fixed by dataset)
#define BATCH   131072
#define UNITS   512
#define DIMK    64
#define M_TILE  128
#define N_TILES (BATCH / M_TILE)   // 1024
#define GRID_X  148
#define NTHREADS 256               // 8 warps; each warp owns a 64-col strip

// ---------------- SMEM layout ----------------
static constexpr int ROW_BYTES = 144;                     // bf16 rows padded (ldmatrix)
static constexpr int SM_WSQ  = 0;                         // 512 f32 -> 2048
static constexpr int SM_XSQ0 = 2048;                      // 128 f32 -> 2560
static constexpr int SM_XSQ1 = 2560;                      // 128 f32 -> 3072
static constexpr int SM_X0   = 3072;                      // 128*144 -> 21504
static constexpr int SM_X1   = 21504;                     // -> 39936
static constexpr int SM_WST  = 39936;                     // 512*144 -> 113664
static constexpr int SM_STG  = 113664;                    // 8 warps * 2 * 4KB -> 179200
static constexpr int SMEM_TOTAL = SM_STG + 8 * 8192;

static __device__ __forceinline__ uint32_t smem_u32(const void* p) {
    uint32_t a;
    asm("{ .reg .u64 t; cvta.to.shared.u64 t, %1; cvt.u32.u64 %0, t; }" : "=r"(a) : "l"(p));
    return a;
}

static __device__ __forceinline__ void ldsm_x4(uint32_t& r0, uint32_t& r1, uint32_t& r2,
                                               uint32_t& r3, uint32_t addr) {
    asm volatile("ldmatrix.sync.aligned.m8n8.x4.shared.b16 {%0,%1,%2,%3}, [%4];"
                 : "=r"(r0), "=r"(r1), "=r"(r2), "=r"(r3) : "r"(addr));
}

static __device__ __forceinline__ void mma_bf16(float c[4], uint32_t a0, uint32_t a1,
                                                uint32_t a2, uint32_t a3,
                                                uint32_t b0, uint32_t b1) {
    asm volatile(
        "mma.sync.aligned.m16n8k16.row.col.f32.bf16.bf16.f32 "
        "{%0,%1,%2,%3}, {%4,%5,%6,%7}, {%8,%9}, {%0,%1,%2,%3};"
        : "+f"(c[0]), "+f"(c[1]), "+f"(c[2]), "+f"(c[3])
        : "r"(a0), "r"(a1), "r"(a2), "r"(a3), "r"(b0), "r"(b1));
}

static __device__ __forceinline__ uint32_t pack_bf16(float a, float b) {
    __nv_bfloat162 t = __floats2bfloat162_rn(a, b);
    return *reinterpret_cast<uint32_t*>(&t);
}

__global__ void __launch_bounds__(NTHREADS, 1)
l2dist_kernel(const float* __restrict__ x, const float* __restrict__ w,
              float* __restrict__ out) {
    extern __shared__ char smem[];
    const uint32_t sb = smem_u32(smem);
    const int tid  = threadIdx.x;
    const int wid  = tid >> 5;
    const int lane = tid & 31;

    const int ld_r0 = tid >> 4;
    const int ld_k  = (tid & 15) * 4;

    int t = blockIdx.x;

    // ---- Issue first tile's x LDG EARLY: latency hides under W staging ----
    float4 fv[8];
    if (t < N_TILES) {
        #pragma unroll
        for (int it = 0; it < 8; it++)
            fv[it] = __ldcs(reinterpret_cast<const float4*>(
                x + (size_t)(t * M_TILE + it * 16 + ld_r0) * DIMK + ld_k));
    }

    // ---- Stage W -> bf16 SMEM (padded rows) + exact fp32 ||w||^2 ----
    #pragma unroll
    for (int rr = 0; rr < 2; rr++) {
        const int u = rr * NTHREADS + tid;
        const float* wr = w + (size_t)u * DIMK;
        float sq = 0.f;
        #pragma unroll
        for (int g = 0; g < 8; g++) {
            float4 a = *reinterpret_cast<const float4*>(wr + 8 * g);
            float4 b = *reinterpret_cast<const float4*>(wr + 8 * g + 4);
            sq += a.x * a.x + a.y * a.y + a.z * a.z + a.w * a.w
                + b.x * b.x + b.y * b.y + b.z * b.z + b.w * b.w;
            uint4 pk;
            pk.x = pack_bf16(a.x, a.y); pk.y = pack_bf16(a.z, a.w);
            pk.z = pack_bf16(b.x, b.y); pk.w = pack_bf16(b.z, b.w);
            *reinterpret_cast<uint4*>(smem + SM_WST + u * ROW_BYTES + g * 16) = pk;
        }
        *reinterpret_cast<float*>(smem + SM_WSQ + u * 4) = sq;
    }
    __syncthreads();

    // ---- Load this warp's B fragments ONCE (64 cols x 64 k) : 64 regs ----
    const int n_w = wid * 64;
    uint32_t Bf[4][4][4];   // [n16-group][ks][frag]
    {
        const uint32_t bb = sb + SM_WST + (uint32_t)(lane & 15) * ROW_BYTES
                          + (uint32_t)((lane >> 4) * 16);
        #pragma unroll
        for (int g = 0; g < 4; g++)
            #pragma unroll
            for (int ks = 0; ks < 4; ks++)
                ldsm_x4(Bf[g][ks][0], Bf[g][ks][1], Bf[g][ks][2], Bf[g][ks][3],
                        bb + (uint32_t)(n_w + g * 16) * ROW_BYTES + ks * 32);
    }

    const int gq = lane >> 2;           // 0..7  (C-frag row within 8-group)
    const int qq = lane & 3;            // 0..3  (C-frag col pair)

    // readback/store mapping: lane covers 4 consecutive cols of 2 rows per iter
    const int rd_row  = lane >> 4;      // 0/1
    const int rd_colg = lane & 15;      // 0..15 -> cols rd_colg*4..+3
    const float4 ws4 = *reinterpret_cast<const float4*>(
        smem + SM_WSQ + (n_w + rd_colg * 4) * 4);

    const uint32_t a_lane_off = (uint32_t)(lane & 15) * ROW_BYTES
                              + (uint32_t)((lane >> 4) * 16);
    char* const stg0 = smem + SM_STG + wid * 8192;   // two 4KB fp32 buffers

    // ---- Commit first tile (data already in registers) ----
    if (t < N_TILES) {
        #pragma unroll
        for (int it = 0; it < 8; it++) {
            const int r = it * 16 + ld_r0;
            float4 v = fv[it];
            float sq = v.x * v.x + v.y * v.y + v.z * v.z + v.w * v.w;
            sq += __shfl_xor_sync(0xffffffffu, sq, 1);
            sq += __shfl_xor_sync(0xffffffffu, sq, 2);
            sq += __shfl_xor_sync(0xffffffffu, sq, 4);
            sq += __shfl_xor_sync(0xffffffffu, sq, 8);
            uint2 pk; pk.x = pack_bf16(v.x, v.y); pk.y = pack_bf16(v.z, v.w);
            *reinterpret_cast<uint2*>(smem + SM_X0 + r * ROW_BYTES + ld_k * 2) = pk;
            if ((tid & 15) == 0)
                *reinterpret_cast<float*>(smem + SM_XSQ0 + r * 4) = sq;
        }
    }
    __syncthreads();

    int cur = 0;
    for (; t < N_TILES; t += GRID_X, cur ^= 1) {
        const int tn = t + GRID_X;
        const bool more = (tn < N_TILES);
        const uint32_t xb = cur ? SM_X1 : SM_X0;
        const uint32_t xq = cur ? SM_XSQ1 : SM_XSQ0;
        const uint32_t xbn = cur ? SM_X0 : SM_X1;
        const uint32_t xqn = cur ? SM_XSQ0 : SM_XSQ1;
        const int row0 = t * M_TILE;

        float4 pvA[4], pvB[4];
        if (more) {
            #pragma unroll
            for (int it = 0; it < 4; it++)
                pvA[it] = __ldcs(reinterpret_cast<const float4*>(
                    x + (size_t)(tn * M_TILE + it * 16 + ld_r0) * DIMK + ld_k));
        }

        #pragma unroll
        for (int rb = 0; rb < 8; rb++) {
            if (rb == 4 && more) {
                #pragma unroll
                for (int it = 0; it < 4; it++)
                    pvB[it] = __ldcs(reinterpret_cast<const float4*>(
                        x + (size_t)(tn * M_TILE + (it + 4) * 16 + ld_r0) * DIMK + ld_k));
            }
            // spread the next-tile commit: first half at rb==6 (pvA freed early)
            if (rb == 6 && more) {
                #pragma unroll
                for (int it = 0; it < 4; it++) {
                    const int r = it * 16 + ld_r0;
                    float4 v = pvA[it];
                    float sq = v.x * v.x + v.y * v.y + v.z * v.z + v.w * v.w;
                    sq += __shfl_xor_sync(0xffffffffu, sq, 1);
                    sq += __shfl_xor_sync(0xffffffffu, sq, 2);
                    sq += __shfl_xor_sync(0xffffffffu, sq, 4);
                    sq += __shfl_xor_sync(0xffffffffu, sq, 8);
                    uint2 pk; pk.x = pack_bf16(v.x, v.y); pk.y = pack_bf16(v.z, v.w);
                    *reinterpret_cast<uint2*>(smem + xbn + r * ROW_BYTES + ld_k * 2) = pk;
                    if ((tid & 15) == 0)
                        *reinterpret_cast<float*>(smem + xqn + r * 4) = sq;
                }
            }

            char* const stg = stg0 + (rb & 1) * 4096;   // double-buffered staging
            const uint32_t abase = sb + xb + (uint32_t)(rb * 16) * ROW_BYTES + a_lane_off;
            float acc[8][4];
            #pragma unroll
            for (int i = 0; i < 8; i++)
                #pragma unroll
                for (int j = 0; j < 4; j++) acc[i][j] = 0.f;

            #pragma unroll
            for (int ks = 0; ks < 4; ks++) {
                uint32_t a0, a1, a2, a3;
                ldsm_x4(a0, a1, a2, a3, abase + ks * 32);
                #pragma unroll
                for (int g = 0; g < 4; g++) {
                    mma_bf16(acc[2 * g + 0], a0, a1, a2, a3, Bf[g][ks][0], Bf[g][ks][2]);
                    mma_bf16(acc[2 * g + 1], a0, a1, a2, a3, Bf[g][ks][1], Bf[g][ks][3]);
                }
            }

            // ---- Stage raw fp32 acc (STS.64), 8B granules h ^= (gq<<2) ----
            #pragma unroll
            for (int nb = 0; nb < 8; nb++) {
                const uint32_t h  = (uint32_t)(gq * 32 + nb * 4 + qq) ^ ((uint32_t)gq << 2);
                const uint32_t hh = h + 8 * 32;   // row gq+8: same swizzle
                *reinterpret_cast<float2*>(stg + h * 8)
                    = make_float2(acc[nb][0], acc[nb][1]);
                *reinterpret_cast<float2*>(stg + hh * 8)
                    = make_float2(acc[nb][2], acc[nb][3]);
            }
            __syncwarp();
            // no trailing syncwarp: next rb uses the other staging buffer

            // ---- Read back row-major (LDS.128), epilogue, full-line STG.128 ----
            #pragma unroll
            for (int i = 0; i < 8; i++) {
                const int row = i * 2 + rd_row;
                const uint32_t g16 = (uint32_t)(row * 16 + rd_colg)
                                   ^ (((uint32_t)(row & 7)) << 1);
                const float4 v = *reinterpret_cast<const float4*>(stg + g16 * 16);
                const float xsv = *reinterpret_cast<const float*>(
                    smem + xq + (rb * 16 + row) * 4);
                float4 o;
                o.x = fmaf(-2.f, v.x, xsv + ws4.x);
                o.y = fmaf(-2.f, v.y, xsv + ws4.y);
                o.z = fmaf(-2.f, v.z, xsv + ws4.z);
                o.w = fmaf(-2.f, v.w, xsv + ws4.w);
                __stcs(reinterpret_cast<float4*>(
                    out + (size_t)(row0 + rb * 16 + row) * UNITS + n_w + rd_colg * 4), o);
            }
        }

        // ---- Commit second half of prefetched tile ----
        if (more) {
            #pragma unroll
            for (int it = 4; it < 8; it++) {
                const int r = it * 16 + ld_r0;
                float4 v = pvB[it - 4];
                float sq = v.x * v.x + v.y * v.y + v.z * v.z + v.w * v.w;
                sq += __shfl_xor_sync(0xffffffffu, sq, 1);
                sq += __shfl_xor_sync(0xffffffffu, sq, 2);
                sq += __shfl_xor_sync(0xffffffffu, sq, 4);
                sq += __shfl_xor_sync(0xffffffffu, sq, 8);
                uint2 pk; pk.x = pack_bf16(v.x, v.y); pk.y = pack_bf16(v.z, v.w);
                *reinterpret_cast<uint2*>(smem + xbn + r * ROW_BYTES + ld_k * 2) = pk;
                if ((tid & 15) == 0)
                    *reinterpret_cast<float*>(smem + xqn + r * 4) = sq;
            }
        }
        __syncthreads();
    }
}

extern "C" void kernel_launch(void* const* d_in, const int* in_sizes, int n_in,
                              void* d_out, int out_size) {
    const float* x = (const float*)d_in[0];
    const float* w = (const float*)d_in[1];
    float* out = (float*)d_out;
    cudaFuncSetAttribute(l2dist_kernel, cudaFuncAttributeMaxDynamicSharedMemorySize, SMEM_TOTAL);
    l2dist_kernel<<<GRID_X, NTHREADS, SMEM_TOTAL>>>(x, w, out);
}